// round 1
// baseline (speedup 1.0000x reference)
#include <cuda_runtime.h>
#include <math.h>

// Problem constants
#define BB 2
#define TT 2048
#define CC 1024
#define HH 16
#define HDIM 64
#define BT (BB * TT)      // 4096 rows
#define LOG2T 11

// ----------------------------------------------------------------------------
// Device scratch (static; no allocations allowed)
// ----------------------------------------------------------------------------
static __device__ float g_q[BT * CC];
static __device__ float g_k[BT * CC];
static __device__ float g_v[BT * CC];
static __device__ float g_qr[BT * CC];
static __device__ float g_qi[BT * CC];
static __device__ float g_kr[BT * CC];
static __device__ float g_ki[BT * CC];
static __device__ float g_vr[BT * CC];
static __device__ float g_att[BT * CC];
static __device__ float g_y[BT * CC];
static __device__ float g_inE[BT];

// ----------------------------------------------------------------------------
// Reductions
// ----------------------------------------------------------------------------
__device__ __forceinline__ float blockReduceSum256(float v) {
    __shared__ float red[8];
    int lane = threadIdx.x & 31;
    int w = threadIdx.x >> 5;
#pragma unroll
    for (int o = 16; o >= 1; o >>= 1)
        v += __shfl_xor_sync(0xffffffffu, v, o);
    if (lane == 0) red[w] = v;
    __syncthreads();
    if (w == 0) {
        v = (lane < 8) ? red[lane] : 0.f;
#pragma unroll
        for (int o = 4; o >= 1; o >>= 1)
            v += __shfl_xor_sync(0xffffffffu, v, o);
    }
    return v;  // valid in thread 0
}

// ----------------------------------------------------------------------------
// Input energy: ||x[b,t,:]||_2
// ----------------------------------------------------------------------------
__global__ void energy_in_kernel(const float* __restrict__ x) {
    int row = blockIdx.x;
    const float* xr = x + (size_t)row * CC;
    float s = 0.f;
    for (int c = threadIdx.x; c < CC; c += 256) {
        float v = xr[c];
        s += v * v;
    }
    float tot = blockReduceSum256(s);
    if (threadIdx.x == 0) g_inE[row] = sqrtf(tot);
}

// ----------------------------------------------------------------------------
// GEMM: C[4096,1024] = A[4096,1024] @ W[1024,1024] + bias
// 64x64 tile, BK=16, 256 threads, 4x4 register tile per thread
// ----------------------------------------------------------------------------
__global__ void gemm4096_kernel(const float* __restrict__ A,
                                const float* __restrict__ W,
                                const float* __restrict__ bias,
                                float* __restrict__ Co) {
    __shared__ __align__(16) float As[16][68];
    __shared__ __align__(16) float Bs[16][68];
    const int tid = threadIdx.x;
    const int ty = tid >> 4, tx = tid & 15;
    const int m0 = blockIdx.y << 6, n0 = blockIdx.x << 6;
    float acc[4][4] = {};
    for (int k0 = 0; k0 < CC; k0 += 16) {
#pragma unroll
        for (int i = 0; i < 4; i++) {
            int e = tid + i * 256;
            int r = e >> 4, kk = e & 15;
            As[kk][r] = A[(size_t)(m0 + r) * CC + k0 + kk];
            int r2 = e >> 6, c2 = e & 63;
            Bs[r2][c2] = W[(size_t)(k0 + r2) * CC + n0 + c2];
        }
        __syncthreads();
#pragma unroll
        for (int kk = 0; kk < 16; kk++) {
            float4 a4 = *(const float4*)&As[kk][ty * 4];
            float4 b4 = *(const float4*)&Bs[kk][tx * 4];
            float av[4] = {a4.x, a4.y, a4.z, a4.w};
            float bv[4] = {b4.x, b4.y, b4.z, b4.w};
#pragma unroll
            for (int i = 0; i < 4; i++)
#pragma unroll
                for (int j = 0; j < 4; j++)
                    acc[i][j] += av[i] * bv[j];
        }
        __syncthreads();
    }
#pragma unroll
    for (int i = 0; i < 4; i++) {
#pragma unroll
        for (int j = 0; j < 4; j++) {
            Co[(size_t)(m0 + ty * 4 + i) * CC + n0 + tx * 4 + j] =
                acc[i][j] + bias[n0 + tx * 4 + j];
        }
    }
}

// ----------------------------------------------------------------------------
// FFT (2048-pt complex, radix-2 DIT) + spectral filter, one block per (b,h,d).
// Input layout [b,t,C] (head h, dim d at column h*64+d).
// Output layout [b,h,t,d]. outIm may be null (V path needs only Re).
// ----------------------------------------------------------------------------
__global__ void fft_filter_kernel(const float* __restrict__ in,
                                  float* __restrict__ outRe,
                                  float* __restrict__ outIm,
                                  const float* __restrict__ fd,
                                  const float* __restrict__ alpha,
                                  const float* __restrict__ fas) {
    __shared__ float2 sh[TT];
    const int d = blockIdx.x, h = blockIdx.y, b = blockIdx.z;
    const float* src = in + (size_t)b * TT * CC + h * HDIM + d;
    const int tid = threadIdx.x;

    // bit-reversed load (real input)
#pragma unroll
    for (int i = 0; i < 8; i++) {
        int t = tid + i * 256;
        unsigned r = __brev((unsigned)t) >> (32 - LOG2T);
        sh[r] = make_float2(src[(size_t)t * CC], 0.f);
    }
    __syncthreads();

    // forward FFT, numpy sign convention exp(-2*pi*i*k*n/N)
    for (int st = 1; st <= LOG2T; st++) {
        const int half = 1 << (st - 1);
        const float wstep = -6.283185307179586f / (float)(half * 2);
#pragma unroll
        for (int i = 0; i < 4; i++) {
            int idx = tid + i * 256;
            int pos = idx & (half - 1);
            int grp = idx >> (st - 1);
            int i0 = (grp << st) + pos;
            int i1 = i0 + half;
            float sn, cs;
            sincosf(wstep * (float)pos, &sn, &cs);
            float2 u = sh[i0], v = sh[i1];
            float tr = cs * v.x - sn * v.y;
            float ti = cs * v.y + sn * v.x;
            sh[i0] = make_float2(u.x + tr, u.y + ti);
            sh[i1] = make_float2(u.x - tr, u.y - ti);
        }
        __syncthreads();
    }

    // spectral filter exp(i * phase), phase = a * atan(log(|f| + 1e-10))
    const float aal = alpha[0] + fas[0] * (fd[0] - 1.5f);
    const size_t obase = ((size_t)(b * HH + h)) * TT * HDIM + d;
#pragma unroll
    for (int i = 0; i < 8; i++) {
        int t = tid + i * 256;
        float fr = (float)(t < TT / 2 ? t : t - TT) * (1.0f / (float)TT);
        float phase = aal * atanf(logf(fabsf(fr) + 1e-10f));
        float sp, cp;
        sincosf(phase, &sp, &cp);
        float2 X = sh[t];
        size_t o = obase + (size_t)t * HDIM;
        outRe[o] = X.x * cp - X.y * sp;
        if (outIm) outIm[o] = X.x * sp + X.y * cp;
    }
}

// ----------------------------------------------------------------------------
// Flash-style attention per (b,h): S = (Qr Kr^T - Qi Ki^T)/8, online softmax,
// O = P @ Vr. 64x64 tiles, 256 threads, 4x4 per-thread register tile.
// Q/K kept d-major (transposed) in smem, pad 68 -> conflict-free float4 frags.
// Output written in [b,t,h,d] layout (ready for the out-proj GEMM).
// ----------------------------------------------------------------------------
__global__ void attn_kernel(const float* __restrict__ Qr, const float* __restrict__ Qi,
                            const float* __restrict__ Kr, const float* __restrict__ Ki,
                            const float* __restrict__ Vr, float* __restrict__ Ao) {
    extern __shared__ __align__(16) float smbuf[];
    float* sQr = smbuf;                 // [d=64][68]
    float* sQi = sQr + 64 * 68;
    float* sKr = sQi + 64 * 68;        // [d=64][68]
    float* sKi = sKr + 64 * 68;
    float* sVr = sKi + 64 * 68;        // [s=64][68]
    float* sP  = sVr + 64 * 68;        // [t=64][68]

    const int tid = threadIdx.x;
    const int ty = tid >> 4, tx = tid & 15;
    const int t0 = blockIdx.x << 6;
    const int h = blockIdx.y, b = blockIdx.z;
    const size_t base = ((size_t)(b * HH + h)) * TT * HDIM;

    // load Q tile (transposed into [d][t])
#pragma unroll
    for (int i = 0; i < 16; i++) {
        int e = tid + i * 256;
        int r = e >> 6, c = e & 63;
        size_t g = base + (size_t)(t0 + r) * HDIM + c;
        sQr[c * 68 + r] = Qr[g];
        sQi[c * 68 + r] = Qi[g];
    }

    float m[4], l[4], acc[4][4];
#pragma unroll
    for (int i = 0; i < 4; i++) {
        m[i] = -INFINITY;
        l[i] = 0.f;
#pragma unroll
        for (int j = 0; j < 4; j++) acc[i][j] = 0.f;
    }

    for (int s0 = 0; s0 < TT; s0 += 64) {
        __syncthreads();
#pragma unroll
        for (int i = 0; i < 16; i++) {
            int e = tid + i * 256;
            int r = e >> 6, c = e & 63;
            size_t g = base + (size_t)(s0 + r) * HDIM + c;
            sKr[c * 68 + r] = Kr[g];
            sKi[c * 68 + r] = Ki[g];
            sVr[r * 68 + c] = Vr[g];
        }
        __syncthreads();

        // S tile: 4x4 per thread, outer-product over d
        float S[4][4] = {};
#pragma unroll 8
        for (int d = 0; d < 64; d++) {
            float4 q4 = *(const float4*)&sQr[d * 68 + ty * 4];
            float4 p4 = *(const float4*)&sQi[d * 68 + ty * 4];
            float4 k4 = *(const float4*)&sKr[d * 68 + tx * 4];
            float4 j4 = *(const float4*)&sKi[d * 68 + tx * 4];
            float qa[4] = {q4.x, q4.y, q4.z, q4.w};
            float qb[4] = {p4.x, p4.y, p4.z, p4.w};
            float ka[4] = {k4.x, k4.y, k4.z, k4.w};
            float kb[4] = {j4.x, j4.y, j4.z, j4.w};
#pragma unroll
            for (int i = 0; i < 4; i++)
#pragma unroll
                for (int j = 0; j < 4; j++)
                    S[i][j] += qa[i] * ka[j] - qb[i] * kb[j];
        }

        // online softmax (row = ty*4+i, 16 tx-lanes cooperate per row)
#pragma unroll
        for (int i = 0; i < 4; i++) {
#pragma unroll
            for (int j = 0; j < 4; j++) S[i][j] *= 0.125f;
            float mx = fmaxf(fmaxf(S[i][0], S[i][1]), fmaxf(S[i][2], S[i][3]));
#pragma unroll
            for (int o = 8; o >= 1; o >>= 1)
                mx = fmaxf(mx, __shfl_xor_sync(0xffffffffu, mx, o));
            float mn = fmaxf(m[i], mx);
            float corr = __expf(m[i] - mn);
            float ps = 0.f;
#pragma unroll
            for (int j = 0; j < 4; j++) {
                float p = __expf(S[i][j] - mn);
                sP[(ty * 4 + i) * 68 + tx * 4 + j] = p;
                ps += p;
            }
#pragma unroll
            for (int o = 8; o >= 1; o >>= 1)
                ps += __shfl_xor_sync(0xffffffffu, ps, o);
            l[i] = l[i] * corr + ps;
            m[i] = mn;
#pragma unroll
            for (int j = 0; j < 4; j++) acc[i][j] *= corr;
        }
        __syncthreads();

        // O += P @ V
#pragma unroll 8
        for (int j = 0; j < 64; j++) {
            float4 v4 = *(const float4*)&sVr[j * 68 + tx * 4];
            float va[4] = {v4.x, v4.y, v4.z, v4.w};
#pragma unroll
            for (int i = 0; i < 4; i++) {
                float p = sP[(ty * 4 + i) * 68 + j];
#pragma unroll
                for (int c = 0; c < 4; c++) acc[i][c] += p * va[c];
            }
        }
    }

    // epilogue: normalize and write [b, t, h*64+d]
#pragma unroll
    for (int i = 0; i < 4; i++) {
        float inv = 1.f / l[i];
#pragma unroll
        for (int c = 0; c < 4; c++) {
            size_t o = ((size_t)(b * TT + t0 + ty * 4 + i)) * CC + h * HDIM + tx * 4 + c;
            Ao[o] = acc[i][c] * inv;
        }
    }
}

// ----------------------------------------------------------------------------
// Final energy ratio: out = Y * (inE / (||Y row|| + 1e-8)) * energy_normalizer
// ----------------------------------------------------------------------------
__global__ void finalize_kernel(const float* __restrict__ Y,
                                const float* __restrict__ enorm,
                                float* __restrict__ out) {
    int row = blockIdx.x;
    const float* yr = Y + (size_t)row * CC;
    float s = 0.f;
    for (int c = threadIdx.x; c < CC; c += 256) {
        float v = yr[c];
        s += v * v;
    }
    float tot = blockReduceSum256(s);
    __shared__ float ratio;
    if (threadIdx.x == 0)
        ratio = g_inE[row] / (sqrtf(tot) + 1e-8f) * enorm[0];
    __syncthreads();
    for (int c = threadIdx.x; c < CC; c += 256)
        out[(size_t)row * CC + c] = yr[c] * ratio;
}

// ----------------------------------------------------------------------------
// Launch
// ----------------------------------------------------------------------------
extern "C" void kernel_launch(void* const* d_in, const int* in_sizes, int n_in,
                              void* d_out, int out_size) {
    const float* x      = (const float*)d_in[0];
    const float* fd     = (const float*)d_in[1];
    const float* wq     = (const float*)d_in[2];
    const float* bq     = (const float*)d_in[3];
    const float* wk     = (const float*)d_in[4];
    const float* bk     = (const float*)d_in[5];
    const float* wv     = (const float*)d_in[6];
    const float* bv     = (const float*)d_in[7];
    const float* wo     = (const float*)d_in[8];
    const float* bo     = (const float*)d_in[9];
    const float* alpha  = (const float*)d_in[10];
    const float* fas    = (const float*)d_in[11];
    const float* enorm  = (const float*)d_in[12];
    float* out = (float*)d_out;

    float *q, *k, *v, *qr, *qi, *kr, *ki, *vr, *att, *y;
    cudaGetSymbolAddress((void**)&q,  g_q);
    cudaGetSymbolAddress((void**)&k,  g_k);
    cudaGetSymbolAddress((void**)&v,  g_v);
    cudaGetSymbolAddress((void**)&qr, g_qr);
    cudaGetSymbolAddress((void**)&qi, g_qi);
    cudaGetSymbolAddress((void**)&kr, g_kr);
    cudaGetSymbolAddress((void**)&ki, g_ki);
    cudaGetSymbolAddress((void**)&vr, g_vr);
    cudaGetSymbolAddress((void**)&att, g_att);
    cudaGetSymbolAddress((void**)&y,  g_y);

    // input energies
    energy_in_kernel<<<BT, 256>>>(x);

    // QKV projections
    dim3 gg(CC / 64, BT / 64);
    gemm4096_kernel<<<gg, 256>>>(x, wq, bq, q);
    gemm4096_kernel<<<gg, 256>>>(x, wk, bk, k);
    gemm4096_kernel<<<gg, 256>>>(x, wv, bv, v);

    // FFT + spectral filter (V needs only the real part downstream)
    dim3 gf(HDIM, HH, BB);
    fft_filter_kernel<<<gf, 256>>>(q, qr, qi, fd, alpha, fas);
    fft_filter_kernel<<<gf, 256>>>(k, kr, ki, fd, alpha, fas);
    fft_filter_kernel<<<gf, 256>>>(v, vr, nullptr, fd, alpha, fas);

    // attention
    static const int kAttnSmem = 6 * 64 * 68 * (int)sizeof(float);  // 104448 B
    cudaFuncSetAttribute(attn_kernel, cudaFuncAttributeMaxDynamicSharedMemorySize,
                         kAttnSmem);
    dim3 ga(TT / 64, HH, BB);
    attn_kernel<<<ga, 256, kAttnSmem>>>(qr, qi, kr, ki, vr, att);

    // output projection
    gemm4096_kernel<<<gg, 256>>>(att, wo, bo, y);

    // energy-ratio epilogue
    finalize_kernel<<<BT, 256>>>(y, enorm, out);
}

// round 2
// speedup vs baseline: 1.1013x; 1.1013x over previous
#include <cuda_runtime.h>
#include <math.h>

// Problem constants
#define BB 2
#define TT 2048
#define CC 1024
#define HH 16
#define HDIM 64
#define BT (BB * TT)      // 4096 rows
#define LOG2T 11

// ----------------------------------------------------------------------------
// Device scratch (static; no allocations allowed)
// ----------------------------------------------------------------------------
static __device__ float g_q[BT * CC];
static __device__ float g_k[BT * CC];
static __device__ float g_v[BT * CC];
static __device__ float g_qr[BT * CC];
static __device__ float g_qi[BT * CC];
static __device__ float g_kr[BT * CC];
static __device__ float g_ki[BT * CC];
static __device__ float g_vr[BT * CC];
static __device__ float g_att[BT * CC];
static __device__ float g_y[BT * CC];
static __device__ float g_inE[BT];

// ----------------------------------------------------------------------------
// Reductions
// ----------------------------------------------------------------------------
__device__ __forceinline__ float blockReduceSum256(float v) {
    __shared__ float red[8];
    int lane = threadIdx.x & 31;
    int w = threadIdx.x >> 5;
#pragma unroll
    for (int o = 16; o >= 1; o >>= 1)
        v += __shfl_xor_sync(0xffffffffu, v, o);
    if (lane == 0) red[w] = v;
    __syncthreads();
    if (w == 0) {
        v = (lane < 8) ? red[lane] : 0.f;
#pragma unroll
        for (int o = 4; o >= 1; o >>= 1)
            v += __shfl_xor_sync(0xffffffffu, v, o);
    }
    return v;  // valid in thread 0
}

// ----------------------------------------------------------------------------
// Input energy: ||x[b,t,:]||_2
// ----------------------------------------------------------------------------
__global__ void energy_in_kernel(const float* __restrict__ x) {
    int row = blockIdx.x;
    const float* xr = x + (size_t)row * CC;
    float s = 0.f;
    for (int c = threadIdx.x; c < CC; c += 256) {
        float v = xr[c];
        s += v * v;
    }
    float tot = blockReduceSum256(s);
    if (threadIdx.x == 0) g_inE[row] = sqrtf(tot);
}

// ----------------------------------------------------------------------------
// GEMM: C[4096,1024] = A[4096,1024] @ W[1024,1024] + bias
// 128x128 tile, BK=16, 256 threads, 8x8 register tile per thread (1 B/FMA)
// ----------------------------------------------------------------------------
__global__ void gemm4096_kernel(const float* __restrict__ A,
                                const float* __restrict__ W,
                                const float* __restrict__ bias,
                                float* __restrict__ Co) {
    __shared__ __align__(16) float As[16][132];
    __shared__ __align__(16) float Bs[16][132];
    const int tid = threadIdx.x;
    const int ty = tid >> 4, tx = tid & 15;
    const int m0 = blockIdx.y << 7, n0 = blockIdx.x << 7;
    float acc[8][8] = {};

    for (int k0 = 0; k0 < CC; k0 += 16) {
#pragma unroll
        for (int i = 0; i < 2; i++) {
            int e = tid + i * 256;              // 0..511
            int r = e >> 2, k4 = (e & 3) << 2;  // A: 128 rows x 16 k
            float4 av = *(const float4*)&A[(size_t)(m0 + r) * CC + k0 + k4];
            As[k4 + 0][r] = av.x;
            As[k4 + 1][r] = av.y;
            As[k4 + 2][r] = av.z;
            As[k4 + 3][r] = av.w;
            int rb = e >> 5, c4 = (e & 31) << 2;  // B: 16 rows x 128 cols
            *(float4*)&Bs[rb][c4] =
                *(const float4*)&W[(size_t)(k0 + rb) * CC + n0 + c4];
        }
        __syncthreads();
#pragma unroll
        for (int kk = 0; kk < 16; kk++) {
            float4 a0 = *(const float4*)&As[kk][ty << 2];
            float4 a1 = *(const float4*)&As[kk][64 + (ty << 2)];
            float4 b0 = *(const float4*)&Bs[kk][tx << 2];
            float4 b1 = *(const float4*)&Bs[kk][64 + (tx << 2)];
            float av[8] = {a0.x, a0.y, a0.z, a0.w, a1.x, a1.y, a1.z, a1.w};
            float bv[8] = {b0.x, b0.y, b0.z, b0.w, b1.x, b1.y, b1.z, b1.w};
#pragma unroll
            for (int i = 0; i < 8; i++)
#pragma unroll
                for (int j = 0; j < 8; j++)
                    acc[i][j] += av[i] * bv[j];
        }
        __syncthreads();
    }
#pragma unroll
    for (int i = 0; i < 8; i++) {
        int row = m0 + ((i < 4) ? (ty << 2) + i : 64 + (ty << 2) + i - 4);
#pragma unroll
        for (int jh = 0; jh < 2; jh++) {
            int col = n0 + jh * 64 + (tx << 2);
            float4 o;
            o.x = acc[i][jh * 4 + 0] + bias[col + 0];
            o.y = acc[i][jh * 4 + 1] + bias[col + 1];
            o.z = acc[i][jh * 4 + 2] + bias[col + 2];
            o.w = acc[i][jh * 4 + 3] + bias[col + 3];
            *(float4*)&Co[(size_t)row * CC + col] = o;
        }
    }
}

// ----------------------------------------------------------------------------
// FFT (2048-pt complex, radix-2 DIT) + spectral filter, one block per (b,h,d).
// ----------------------------------------------------------------------------
__global__ void fft_filter_kernel(const float* __restrict__ in,
                                  float* __restrict__ outRe,
                                  float* __restrict__ outIm,
                                  const float* __restrict__ fd,
                                  const float* __restrict__ alpha,
                                  const float* __restrict__ fas) {
    __shared__ float2 sh[TT];
    const int d = blockIdx.x, h = blockIdx.y, b = blockIdx.z;
    const float* src = in + (size_t)b * TT * CC + h * HDIM + d;
    const int tid = threadIdx.x;

#pragma unroll
    for (int i = 0; i < 8; i++) {
        int t = tid + i * 256;
        unsigned r = __brev((unsigned)t) >> (32 - LOG2T);
        sh[r] = make_float2(src[(size_t)t * CC], 0.f);
    }
    __syncthreads();

    for (int st = 1; st <= LOG2T; st++) {
        const int half = 1 << (st - 1);
        const float wstep = -6.283185307179586f / (float)(half * 2);
#pragma unroll
        for (int i = 0; i < 4; i++) {
            int idx = tid + i * 256;
            int pos = idx & (half - 1);
            int grp = idx >> (st - 1);
            int i0 = (grp << st) + pos;
            int i1 = i0 + half;
            float sn, cs;
            __sincosf(wstep * (float)pos, &sn, &cs);
            float2 u = sh[i0], v = sh[i1];
            float tr = cs * v.x - sn * v.y;
            float ti = cs * v.y + sn * v.x;
            sh[i0] = make_float2(u.x + tr, u.y + ti);
            sh[i1] = make_float2(u.x - tr, u.y - ti);
        }
        __syncthreads();
    }

    const float aal = alpha[0] + fas[0] * (fd[0] - 1.5f);
    const size_t obase = ((size_t)(b * HH + h)) * TT * HDIM + d;
#pragma unroll
    for (int i = 0; i < 8; i++) {
        int t = tid + i * 256;
        float fr = (float)(t < TT / 2 ? t : t - TT) * (1.0f / (float)TT);
        float phase = aal * atanf(logf(fabsf(fr) + 1e-10f));
        float sp, cp;
        sincosf(phase, &sp, &cp);
        float2 X = sh[t];
        size_t o = obase + (size_t)t * HDIM;
        outRe[o] = X.x * cp - X.y * sp;
        if (outIm) outIm[o] = X.x * sp + X.y * cp;
    }
}

// ----------------------------------------------------------------------------
// Flash attention per (b,h): S = (Qr Kr^T - Qi Ki^T)/8, online softmax, O=P@Vr.
// 128x128 tiles, 256 threads, 8x8 S register tile (1 B/FMA), 8x4 PV tile.
// P tile (128x132) aliases the Kr+Ki smem region (exactly same size).
// ----------------------------------------------------------------------------
__global__ void attn_kernel(const float* __restrict__ Qr, const float* __restrict__ Qi,
                            const float* __restrict__ Kr, const float* __restrict__ Ki,
                            const float* __restrict__ Vr, float* __restrict__ Ao) {
    extern __shared__ __align__(16) float smbuf[];
    float* sQr = smbuf;                 // [d=64][132] (t-major cols 0..127)
    float* sQi = sQr + 64 * 132;
    float* sKr = sQi + 64 * 132;        // [d=64][132]
    float* sKi = sKr + 64 * 132;
    float* sV  = sKi + 64 * 132;        // [s=128][68]
    float* sP  = sKr;                   // [t=128][132], aliases Kr+Ki

    const int tid = threadIdx.x;
    const int ty = tid >> 4, tx = tid & 15;
    const int t0 = blockIdx.x << 7;
    const int h = blockIdx.y, b = blockIdx.z;
    const size_t base = ((size_t)(b * HH + h)) * TT * HDIM;

    // row/col index helpers for the split 4+4 fragments
    int rowIdx[8], colIdx[8];
#pragma unroll
    for (int i = 0; i < 8; i++) {
        rowIdx[i] = (i < 4) ? (ty << 2) + i : 64 + (ty << 2) + (i - 4);
        colIdx[i] = (i < 4) ? (tx << 2) + i : 64 + (tx << 2) + (i - 4);
    }

    // load Q tile (transposed into [d][t]); 128 rows x 64 d, float4 per 16 cols
#pragma unroll
    for (int i = 0; i < 8; i++) {
        int e = tid + i * 256;          // 0..2047
        int r = e >> 4, c4 = (e & 15) << 2;
        size_t g = base + (size_t)(t0 + r) * HDIM + c4;
        float4 qr = *(const float4*)&Qr[g];
        float4 qi = *(const float4*)&Qi[g];
        sQr[(c4 + 0) * 132 + r] = qr.x;
        sQr[(c4 + 1) * 132 + r] = qr.y;
        sQr[(c4 + 2) * 132 + r] = qr.z;
        sQr[(c4 + 3) * 132 + r] = qr.w;
        sQi[(c4 + 0) * 132 + r] = qi.x;
        sQi[(c4 + 1) * 132 + r] = qi.y;
        sQi[(c4 + 2) * 132 + r] = qi.z;
        sQi[(c4 + 3) * 132 + r] = qi.w;
    }

    float m[8], l[8], acc[8][4];
#pragma unroll
    for (int i = 0; i < 8; i++) {
        m[i] = -INFINITY;
        l[i] = 0.f;
#pragma unroll
        for (int j = 0; j < 4; j++) acc[i][j] = 0.f;
    }

    for (int s0 = 0; s0 < TT; s0 += 128) {
        __syncthreads();  // P/V consumed (and Q visible on first iter)
#pragma unroll
        for (int i = 0; i < 8; i++) {
            int e = tid + i * 256;
            int r = e >> 4, c4 = (e & 15) << 2;
            size_t g = base + (size_t)(s0 + r) * HDIM + c4;
            float4 kr = *(const float4*)&Kr[g];
            float4 ki = *(const float4*)&Ki[g];
            sKr[(c4 + 0) * 132 + r] = kr.x;
            sKr[(c4 + 1) * 132 + r] = kr.y;
            sKr[(c4 + 2) * 132 + r] = kr.z;
            sKr[(c4 + 3) * 132 + r] = kr.w;
            sKi[(c4 + 0) * 132 + r] = ki.x;
            sKi[(c4 + 1) * 132 + r] = ki.y;
            sKi[(c4 + 2) * 132 + r] = ki.z;
            sKi[(c4 + 3) * 132 + r] = ki.w;
            *(float4*)&sV[r * 68 + c4] = *(const float4*)&Vr[g];
        }
        __syncthreads();

        // ---- S tile: 8x8 per thread, outer product over d ----
        float S[8][8] = {};
#pragma unroll 4
        for (int d = 0; d < 64; d++) {
            const float* qrp = &sQr[d * 132 + (ty << 2)];
            const float* qip = &sQi[d * 132 + (ty << 2)];
            const float* krp = &sKr[d * 132 + (tx << 2)];
            const float* kip = &sKi[d * 132 + (tx << 2)];
            float4 a0 = *(const float4*)qrp;
            float4 a1 = *(const float4*)(qrp + 64);
            float4 c0 = *(const float4*)qip;
            float4 c1 = *(const float4*)(qip + 64);
            float4 b0 = *(const float4*)krp;
            float4 b1 = *(const float4*)(krp + 64);
            float4 e0 = *(const float4*)kip;
            float4 e1 = *(const float4*)(kip + 64);
            float qa[8] = {a0.x, a0.y, a0.z, a0.w, a1.x, a1.y, a1.z, a1.w};
            float qb[8] = {c0.x, c0.y, c0.z, c0.w, c1.x, c1.y, c1.z, c1.w};
            float ka[8] = {b0.x, b0.y, b0.z, b0.w, b1.x, b1.y, b1.z, b1.w};
            float kb[8] = {e0.x, e0.y, e0.z, e0.w, e1.x, e1.y, e1.z, e1.w};
#pragma unroll
            for (int i = 0; i < 8; i++)
#pragma unroll
                for (int j = 0; j < 8; j++)
                    S[i][j] += qa[i] * ka[j] - qb[i] * kb[j];
        }
        __syncthreads();  // all K reads done before P overwrites that smem

        // ---- online softmax; write P into aliased smem ----
#pragma unroll
        for (int i = 0; i < 8; i++) {
            float mx = S[i][0];
#pragma unroll
            for (int j = 1; j < 8; j++) mx = fmaxf(mx, S[i][j]);
            mx *= 0.125f;
#pragma unroll
            for (int o = 8; o >= 1; o >>= 1)
                mx = fmaxf(mx, __shfl_xor_sync(0xffffffffu, mx, o));
            float mn = fmaxf(m[i], mx);
            float corr = __expf(m[i] - mn);
            float ps = 0.f;
            float4 p0, p1;
            float pv[8];
#pragma unroll
            for (int j = 0; j < 8; j++) {
                float p = __expf(S[i][j] * 0.125f - mn);
                pv[j] = p;
                ps += p;
            }
            p0 = make_float4(pv[0], pv[1], pv[2], pv[3]);
            p1 = make_float4(pv[4], pv[5], pv[6], pv[7]);
            *(float4*)&sP[rowIdx[i] * 132 + (tx << 2)] = p0;
            *(float4*)&sP[rowIdx[i] * 132 + 64 + (tx << 2)] = p1;
#pragma unroll
            for (int o = 8; o >= 1; o >>= 1)
                ps += __shfl_xor_sync(0xffffffffu, ps, o);
            l[i] = l[i] * corr + ps;
            m[i] = mn;
#pragma unroll
            for (int j = 0; j < 4; j++) acc[i][j] *= corr;
        }
        __syncthreads();

        // ---- O += P @ V (8x4 per thread) ----
#pragma unroll 4
        for (int s = 0; s < 128; s++) {
            float4 v4 = *(const float4*)&sV[s * 68 + (tx << 2)];
#pragma unroll
            for (int i = 0; i < 8; i++) {
                float p = sP[rowIdx[i] * 132 + s];
                acc[i][0] += p * v4.x;
                acc[i][1] += p * v4.y;
                acc[i][2] += p * v4.z;
                acc[i][3] += p * v4.w;
            }
        }
    }

    // epilogue: normalize and write [b, t, h*64+d]
#pragma unroll
    for (int i = 0; i < 8; i++) {
        float inv = 1.f / l[i];
        float4 o;
        o.x = acc[i][0] * inv;
        o.y = acc[i][1] * inv;
        o.z = acc[i][2] * inv;
        o.w = acc[i][3] * inv;
        size_t off = ((size_t)(b * TT + t0 + rowIdx[i])) * CC + h * HDIM + (tx << 2);
        *(float4*)&Ao[off] = o;
    }
}

// ----------------------------------------------------------------------------
// Final energy ratio: out = Y * (inE / (||Y row|| + 1e-8)) * energy_normalizer
// ----------------------------------------------------------------------------
__global__ void finalize_kernel(const float* __restrict__ Y,
                                const float* __restrict__ enorm,
                                float* __restrict__ out) {
    int row = blockIdx.x;
    const float* yr = Y + (size_t)row * CC;
    float s = 0.f;
    for (int c = threadIdx.x; c < CC; c += 256) {
        float v = yr[c];
        s += v * v;
    }
    float tot = blockReduceSum256(s);
    __shared__ float ratio;
    if (threadIdx.x == 0)
        ratio = g_inE[row] / (sqrtf(tot) + 1e-8f) * enorm[0];
    __syncthreads();
    for (int c = threadIdx.x; c < CC; c += 256)
        out[(size_t)row * CC + c] = yr[c] * ratio;
}

// ----------------------------------------------------------------------------
// Launch
// ----------------------------------------------------------------------------
extern "C" void kernel_launch(void* const* d_in, const int* in_sizes, int n_in,
                              void* d_out, int out_size) {
    const float* x      = (const float*)d_in[0];
    const float* fd     = (const float*)d_in[1];
    const float* wq     = (const float*)d_in[2];
    const float* bq     = (const float*)d_in[3];
    const float* wk     = (const float*)d_in[4];
    const float* bk     = (const float*)d_in[5];
    const float* wv     = (const float*)d_in[6];
    const float* bv     = (const float*)d_in[7];
    const float* wo     = (const float*)d_in[8];
    const float* bo     = (const float*)d_in[9];
    const float* alpha  = (const float*)d_in[10];
    const float* fas    = (const float*)d_in[11];
    const float* enorm  = (const float*)d_in[12];
    float* out = (float*)d_out;

    float *q, *k, *v, *qr, *qi, *kr, *ki, *vr, *att, *y;
    cudaGetSymbolAddress((void**)&q,  g_q);
    cudaGetSymbolAddress((void**)&k,  g_k);
    cudaGetSymbolAddress((void**)&v,  g_v);
    cudaGetSymbolAddress((void**)&qr, g_qr);
    cudaGetSymbolAddress((void**)&qi, g_qi);
    cudaGetSymbolAddress((void**)&kr, g_kr);
    cudaGetSymbolAddress((void**)&ki, g_ki);
    cudaGetSymbolAddress((void**)&vr, g_vr);
    cudaGetSymbolAddress((void**)&att, g_att);
    cudaGetSymbolAddress((void**)&y,  g_y);

    // input energies
    energy_in_kernel<<<BT, 256>>>(x);

    // QKV projections
    dim3 gg(CC / 128, BT / 128);
    gemm4096_kernel<<<gg, 256>>>(x, wq, bq, q);
    gemm4096_kernel<<<gg, 256>>>(x, wk, bk, k);
    gemm4096_kernel<<<gg, 256>>>(x, wv, bv, v);

    // FFT + spectral filter (V needs only the real part downstream)
    dim3 gf(HDIM, HH, BB);
    fft_filter_kernel<<<gf, 256>>>(q, qr, qi, fd, alpha, fas);
    fft_filter_kernel<<<gf, 256>>>(k, kr, ki, fd, alpha, fas);
    fft_filter_kernel<<<gf, 256>>>(v, vr, nullptr, fd, alpha, fas);

    // attention: smem = (4*64*132 + 128*68) floats = 169,984 B
    static const int kAttnSmem = (4 * 64 * 132 + 128 * 68) * (int)sizeof(float);
    cudaFuncSetAttribute(attn_kernel, cudaFuncAttributeMaxDynamicSharedMemorySize,
                         kAttnSmem);
    dim3 ga(TT / 128, HH, BB);
    attn_kernel<<<ga, 256, kAttnSmem>>>(qr, qi, kr, ki, vr, att);

    // output projection
    gemm4096_kernel<<<gg, 256>>>(att, wo, bo, y);

    // energy-ratio epilogue
    finalize_kernel<<<BT, 256>>>(y, enorm, out);
}